// round 10
// baseline (speedup 1.0000x reference)
#include <cuda_runtime.h>
#include <math.h>

// Problem constants (fixed by setup_inputs)
#define B_  32
#define K_  16
#define T_  30
#define N_  128
#define n_  20
#define NN  (N_ * n_)          // 2560 nodes per batch
#define BK  (B_ * K_)          // 512
#define TASKS (BK * T_)        // 15360 (bk, t) tasks
#define GRID  512
#define BLOCK 256
#define NWARPS (GRID * BLOCK / 32)   // 4096
#define CHUNK0 128             // phase-A nodes per task
#define NSEG   8               // phase-B segments per unresolved task
#define SEGLEN 304             // 8 * 304 = 2432 = NN - CHUNK0

#define YAW_THRESH  1.0471975511965976f   // pi/3
#define INF_F       __int_as_float(0x7f800000)

// Global scratch (static; reset at end of each run for graph replay).
__device__ int g_minbits[T_ * BK];   // [t][bk], int-encoded nonneg float
__device__ int g_queue[TASKS];
__device__ int g_qcnt;
__device__ int g_bar1;
__device__ int g_bar2;

__device__ __forceinline__ float fast_sqrt(float x) {
    float r;
    asm("sqrt.approx.f32 %0, %1;" : "=f"(r) : "f"(x));
    return r;
}

// cost = relu(dist - 2) + relu(|wrap(yaw_n - yaw_p)| - pi/3); masked -> inf.
// yaw = -atan2(dx, dy) is a reflection of the direction angle, so
// |wrapped yaw diff| == angle(u, v) between raw direction vectors
// (segment starts / t = 0 map to direction (0, 1)).
// Exact-zero (no transcendentals): d2 <= 4 AND dot >= 0 AND cross^2 <= 3*dot^2
// (tan(pi/3)^2 == 3); cost >= 0 so a zero finalizes the min.

// Single persistent-wave kernel. All 512 blocks are co-resident
// (__launch_bounds__(256,4) guarantees >= 4 blocks/SM => 592 slots >= 512),
// so software grid barriers cannot deadlock.
__global__ __launch_bounds__(BLOCK, 4)
void consistency_all(const float* __restrict__ preds,
                     const float* __restrict__ cn,
                     const int*   __restrict__ mask,
                     float* __restrict__ out) {
    const int tid  = threadIdx.x;
    const int lane = tid & 31;
    const int wg   = blockIdx.x * (BLOCK / 32) + (tid >> 5);  // global warp id

    // ============ Phase A: fast path, warp-per-(bk,t), first 128 nodes =====
    #pragma unroll
    for (int w = 0; w < 4; ++w) {
        const int task = wg + w * NWARPS;
        if (task >= TASKS) break;
        const int bk = task / T_;
        const int t  = task - bk * T_;
        const int b  = bk >> 4;

        const float2* pp = (const float2*)preds + (size_t)bk * T_;
        const float2  pt = pp[t];
        float vx = 0.0f, vy = 1.0f;           // yaw 0 <-> direction (0, 1)
        if (t != 0) {
            float2 pm = pp[t - 1];
            vx = pt.x - pm.x;
            vy = pt.y - pm.y;
        }

        const float4* cn4 = (const float4*)(cn + (size_t)b * NN * 2);
        const int2*   mk2 = (const int2*)(mask + (size_t)b * NN);

        // lane holds nodes {2l, 2l+1} and {64+2l, 65+2l}
        float4 v0 = cn4[lane];
        float4 v1 = cn4[32 + lane];
        int2   m0 = mk2[lane];
        int2   m1 = mk2[32 + lane];

        // prev-node coords via shuffles (lane l-1 holds node idx-1)
        float p0x = __shfl_up_sync(0xffffffffu, v0.z, 1);
        float p0y = __shfl_up_sync(0xffffffffu, v0.w, 1);
        float p1x = __shfl_up_sync(0xffffffffu, v1.z, 1);
        float p1y = __shfl_up_sync(0xffffffffu, v1.w, 1);
        float l31x = __shfl_sync(0xffffffffu, v0.z, 31);  // node 63
        float l31y = __shfl_sync(0xffffffffu, v0.w, 31);
        if (lane == 0) { p1x = l31x; p1y = l31y; }

        const int lm10 = lane % 10;
        // starts (idx % 20 == 0): node0 iff lane%10==0; node2 iff lane%10==8;
        // odd-index nodes never.
        float d2[4], dt[4], cr[4];
        bool  z[4];

#define EVAL(i, X, Y, MASKED, START, QX, QY) do {                         \
        float ux = (START) ? 0.0f : (X) - (QX);                           \
        float uy = (START) ? 1.0f : (Y) - (QY);                           \
        float xx = (MASKED) ? INF_F : (X);                                \
        float dx = xx - pt.x, dy = (Y) - pt.y;                            \
        d2[i] = fmaf(dx, dx, dy * dy);                                    \
        dt[i] = fmaf(ux, vx, uy * vy);                                    \
        cr[i] = fmaf(ux, vy, -uy * vx);                                   \
        z[i]  = (d2[i] <= 4.0f) && (dt[i] >= 0.0f) &&                     \
                (cr[i] * cr[i] <= 3.0f * dt[i] * dt[i]);                  \
    } while (0)

        EVAL(0, v0.x, v0.y, m0.x == 1, lm10 == 0, p0x,  p0y);
        EVAL(1, v0.z, v0.w, m0.y == 1, false,     v0.x, v0.y);
        EVAL(2, v1.x, v1.y, m1.x == 1, lm10 == 8, p1x,  p1y);
        EVAL(3, v1.z, v1.w, m1.y == 1, false,     v1.x, v1.y);
#undef EVAL

        const bool anyz = z[0] | z[1] | z[2] | z[3];
        if (__ballot_sync(0xffffffffu, anyz)) {
            if (lane == 0) g_minbits[t * BK + bk] = 0;
        } else {
            float lmin = INF_F;
            #pragma unroll
            for (int j = 0; j < 4; ++j) {
                float cd = (d2[j] <= 4.0f) ? 0.0f : (fast_sqrt(d2[j]) - 2.0f);
                float a  = atan2f(fabsf(cr[j]), dt[j]);
                lmin = fminf(lmin, cd + fmaxf(a - YAW_THRESH, 0.0f));
            }
            lmin = fminf(lmin, __shfl_xor_sync(0xffffffffu, lmin, 16));
            lmin = fminf(lmin, __shfl_xor_sync(0xffffffffu, lmin, 8));
            lmin = fminf(lmin, __shfl_xor_sync(0xffffffffu, lmin, 4));
            lmin = fminf(lmin, __shfl_xor_sync(0xffffffffu, lmin, 2));
            lmin = fminf(lmin, __shfl_xor_sync(0xffffffffu, lmin, 1));
            if (lane == 0) {
                g_minbits[t * BK + bk] = __float_as_int(lmin);
                int pos = atomicAdd(&g_qcnt, 1);
                g_queue[pos] = (bk << 5) | t;
            }
        }
    }

    // ============ Grid barrier 1 (all blocks resident => safe) =============
    __threadfence();
    __syncthreads();
    if (tid == 0) {
        atomicAdd(&g_bar1, 1);
        while (*(volatile int*)&g_bar1 < GRID) __nanosleep(64);
    }
    __syncthreads();
    __threadfence();

    // ============ Phase B: globally balanced straggler segments ============
    const int qcnt   = *(volatile int*)&g_qcnt;
    const int nitems = qcnt * NSEG;
    for (int it = wg; it < nitems; it += NWARPS) {
        const int q = it >> 3;
        const int s = it & (NSEG - 1);
        const int code = g_queue[q];
        const int bk = code >> 5;
        const int t  = code & 31;
        const int b  = bk >> 4;

        const float2* cnb = (const float2*)cn + (size_t)b * NN;
        const int*    mb  = mask + (size_t)b * NN;
        const float2* pp  = (const float2*)preds + (size_t)bk * T_;

        const float2 pt = pp[t];
        float vx = 0.0f, vy = 1.0f;
        if (t != 0) {
            float2 pm = pp[t - 1];
            vx = pt.x - pm.x;
            vy = pt.y - pm.y;
        }

        const int segbase = CHUNK0 + s * SEGLEN;
        float lmin = INF_F;
        #pragma unroll
        for (int j = 0; j < 10; ++j) {
            const int off = j * 32 + lane;
            if (off < SEGLEN) {
                const int idx = segbase + off;
                float2 p = cnb[idx];
                float2 qq = cnb[idx - 1];
                int    m = mb[idx];
                bool start = (idx % n_ == 0);
                float ux = start ? 0.0f : p.x - qq.x;
                float uy = start ? 1.0f : p.y - qq.y;
                float x  = (m == 1) ? INF_F : p.x;

                float dx = x - pt.x;
                float dy = p.y - pt.y;
                float d2 = fmaf(dx, dx, dy * dy);
                float dt = fmaf(ux, vx, uy * vy);
                float cr = fmaf(ux, vy, -uy * vx);

                float c;
                if ((d2 <= 4.0f) && (dt >= 0.0f) &&
                    (cr * cr <= 3.0f * dt * dt)) {
                    c = 0.0f;
                } else {
                    float cd = (d2 <= 4.0f) ? 0.0f : (fast_sqrt(d2) - 2.0f);
                    float a  = atan2f(fabsf(cr), dt);
                    c = cd + fmaxf(a - YAW_THRESH, 0.0f);
                }
                lmin = fminf(lmin, c);
            }
        }
        lmin = fminf(lmin, __shfl_xor_sync(0xffffffffu, lmin, 16));
        lmin = fminf(lmin, __shfl_xor_sync(0xffffffffu, lmin, 8));
        lmin = fminf(lmin, __shfl_xor_sync(0xffffffffu, lmin, 4));
        lmin = fminf(lmin, __shfl_xor_sync(0xffffffffu, lmin, 2));
        lmin = fminf(lmin, __shfl_xor_sync(0xffffffffu, lmin, 1));
        // nonnegative floats: int-bit order == float order (deterministic min)
        if (lane == 0) atomicMin(&g_minbits[t * BK + bk], __float_as_int(lmin));
    }

    // ============ Grid barrier 2: only block 0 waits; others exit ==========
    __threadfence();
    __syncthreads();
    if (tid == 0) atomicAdd(&g_bar2, 1);

    if (blockIdx.x == 0) {
        if (tid == 0) {
            while (*(volatile int*)&g_bar2 < GRID) __nanosleep(64);
        }
        __syncthreads();
        __threadfence();

        // sum over T for two bk's per thread (coalesced over bk)
        #pragma unroll
        for (int h = 0; h < 2; ++h) {
            const int bk = tid + h * BLOCK;
            float v = 0.0f;
            #pragma unroll
            for (int t = 0; t < T_; ++t)
                v += __int_as_float(g_minbits[t * BK + bk]);
            out[bk] = v;
        }
        __syncthreads();
        if (tid == 0) {          // reset for next graph replay
            g_qcnt = 0;
            g_bar1 = 0;
            g_bar2 = 0;
        }
    }
}

extern "C" void kernel_launch(void* const* d_in, const int* in_sizes, int n_in,
                              void* d_out, int out_size) {
    const float* preds = (const float*)d_in[0];
    const float* cn    = (const float*)d_in[1];
    const int*   mask  = (const int*)d_in[2];
    float* out = (float*)d_out;

    consistency_all<<<GRID, BLOCK>>>(preds, cn, mask, out);
}

// round 11
// speedup vs baseline: 1.4787x; 1.4787x over previous
#include <cuda_runtime.h>
#include <math.h>

// Problem constants (fixed by setup_inputs)
#define B_  32
#define K_  16
#define T_  30
#define N_  128
#define n_  20
#define NN  (N_ * n_)          // 2560 nodes per batch
#define BK  (B_ * K_)          // 512
#define BLOCK 256
#define CHUNK0 128             // phase-A nodes
#define REST   (NN - CHUNK0)   // 2432
#define NSEG   8
#define SEGLEN (REST / NSEG)   // 304

#define YAW_THRESH  1.0471975511965976f   // pi/3
#define INF_F       __int_as_float(0x7f800000)
#define INF_BITS    0x7f800000

__device__ __forceinline__ float fast_sqrt(float x) {
    float r;
    asm("sqrt.approx.f32 %0, %1;" : "=f"(r) : "f"(x));
    return r;
}

// cost = relu(dist - 2) + relu(|wrap(yaw_n - yaw_p)| - pi/3); masked -> inf.
// yaw = -atan2(dx, dy) reflects the direction angle, so |wrapped yaw diff| ==
// angle(u, v) between raw direction vectors (starts / t = 0 -> dir (0, 1)).
// Exact-zero (no transcendentals): d2 <= 4 AND dot >= 0 AND cross^2 <= 3*dot^2
// (tan(pi/3)^2 == 3); cost >= 0, so any zero finalizes the min.
//
// One block per (b, k), 256 threads = 8 warps:
//  Phase 0: threads 0-127 build s_nd[128] (x|inf, y, ux, uy);
//           threads 128-157 build s_ptv[30] (pt.x, pt.y, vx, vy).
//  Phase A: warp w handles t = w, w+8, w+16, w+24. Nodes live in REGISTERS
//           (4 x LDS.128, loaded once, reused across all 4 timesteps);
//           per t: 1 broadcast LDS.128 + ~50 flops + 1 ballot.
//           Zero hit -> min = 0. Miss (Poisson-rare, ~0.3/block) -> partial
//           min + enqueue.
//  Phase B: flattened (u, seg) items over all 8 warps; nodes [128, 2560)
//           in 8 segments of 304; atomicMin on int-encoded nonneg costs.
__global__ __launch_bounds__(BLOCK)
void consistency_kernel(const float* __restrict__ preds,
                        const float* __restrict__ cn,
                        const int*   __restrict__ mask,
                        float* __restrict__ out) {
    const int bk = blockIdx.x;
    const int b  = bk >> 4;                 // / K_

    const float2* cnb = (const float2*)cn + (size_t)b * NN;
    const int*    mb  = mask + (size_t)b * NN;
    const float2* pp  = (const float2*)preds + (size_t)bk * T_;

    __shared__ float4 s_nd[CHUNK0];         // 2 KB
    __shared__ float4 s_ptv[T_];
    __shared__ int    s_minb[32];
    __shared__ int    s_unres[32];
    __shared__ int    s_ucnt;

    const int tid  = threadIdx.x;
    const int warp = tid >> 5;
    const int lane = tid & 31;

    // ---------------- Phase 0 (split across warps) ----------------
    if (tid < CHUNK0) {
        const int idx = tid;
        float2 p = cnb[idx];
        float2 q = cnb[idx > 0 ? idx - 1 : 0];
        int    m = mb[idx];
        bool start = (idx % n_ == 0);
        float ux = start ? 0.0f : p.x - q.x;
        float uy = start ? 1.0f : p.y - q.y;
        float x  = (m == 1) ? INF_F : p.x;   // masked -> d2 = +inf
        s_nd[idx] = make_float4(x, p.y, ux, uy);
    } else if (tid < 128 + T_) {
        const int t = tid - 128;
        float2 pt = pp[t];
        float vx = 0.0f, vy = 1.0f;          // yaw 0 <-> direction (0, 1)
        if (t != 0) {
            float2 pm = pp[t - 1];
            vx = pt.x - pm.x;
            vy = pt.y - pm.y;
        }
        s_ptv[t] = make_float4(pt.x, pt.y, vx, vy);
    } else if (tid == 128 + T_) {
        s_ucnt = 0;
    } else if (tid >= 192 && tid < 224) {
        s_minb[tid - 192] = (tid - 192 < T_) ? INF_BITS : 0;
    }
    __syncthreads();

    // ---------------- Phase A: nodes in registers, 4 t's per warp ---------
    const float4 nd0 = s_nd[lane];
    const float4 nd1 = s_nd[lane + 32];
    const float4 nd2 = s_nd[lane + 64];
    const float4 nd3 = s_nd[lane + 96];

    #pragma unroll
    for (int i = 0; i < 4; ++i) {
        const int t = warp + i * 8;
        if (t >= T_) break;                  // warps 6,7 do 3 iterations
        const float4 ptv = s_ptv[t];

        float d2[4], dt[4], cr[4];
        bool  anyz = false;

#define ZEVAL(j, ND) do {                                                  \
        float dx = (ND).x - ptv.x;                                         \
        float dy = (ND).y - ptv.y;                                         \
        d2[j] = fmaf(dx, dx, dy * dy);                                     \
        dt[j] = fmaf((ND).z, ptv.z, (ND).w * ptv.w);                       \
        cr[j] = fmaf((ND).z, ptv.w, -(ND).w * ptv.z);                      \
        anyz |= (d2[j] <= 4.0f) && (dt[j] >= 0.0f) &&                      \
                (cr[j] * cr[j] <= 3.0f * dt[j] * dt[j]);                   \
    } while (0)

        ZEVAL(0, nd0);
        ZEVAL(1, nd1);
        ZEVAL(2, nd2);
        ZEVAL(3, nd3);
#undef ZEVAL

        if (__ballot_sync(0xffffffffu, anyz)) {
            if (lane == 0) s_minb[t] = 0;
        } else {
            float lmin = INF_F;
            #pragma unroll
            for (int j = 0; j < 4; ++j) {
                float cd = (d2[j] <= 4.0f) ? 0.0f : (fast_sqrt(d2[j]) - 2.0f);
                float a  = atan2f(fabsf(cr[j]), dt[j]);
                lmin = fminf(lmin, cd + fmaxf(a - YAW_THRESH, 0.0f));
            }
            lmin = fminf(lmin, __shfl_xor_sync(0xffffffffu, lmin, 16));
            lmin = fminf(lmin, __shfl_xor_sync(0xffffffffu, lmin, 8));
            lmin = fminf(lmin, __shfl_xor_sync(0xffffffffu, lmin, 4));
            lmin = fminf(lmin, __shfl_xor_sync(0xffffffffu, lmin, 2));
            lmin = fminf(lmin, __shfl_xor_sync(0xffffffffu, lmin, 1));
            if (lane == 0) {
                s_minb[t] = __float_as_int(lmin);
                int pos = atomicAdd(&s_ucnt, 1);
                s_unres[pos] = t;
            }
        }
    }
    __syncthreads();

    // ---------------- Phase B: flattened straggler segments ---------------
    const int ucnt = s_ucnt;
    if (ucnt > 0) {
        const int nitems = ucnt * NSEG;
        for (int it = warp; it < nitems; it += 8) {
            const int u = it >> 3;
            const int s = it & (NSEG - 1);
            const int t = s_unres[u];
            const float4 ptv = s_ptv[t];

            const int segbase = CHUNK0 + s * SEGLEN;
            float lmin = INF_F;
            for (int off = lane; off < SEGLEN; off += 32) {
                const int idx = segbase + off;
                float2 p = cnb[idx];
                float2 q = cnb[idx - 1];
                int    m = mb[idx];
                bool start = (idx % n_ == 0);
                float ux = start ? 0.0f : p.x - q.x;
                float uy = start ? 1.0f : p.y - q.y;
                float x  = (m == 1) ? INF_F : p.x;

                float dx = x - ptv.x;
                float dy = p.y - ptv.y;
                float d2 = fmaf(dx, dx, dy * dy);
                float dt = fmaf(ux, ptv.z, uy * ptv.w);
                float cr = fmaf(ux, ptv.w, -uy * ptv.z);

                float c;
                if ((d2 <= 4.0f) && (dt >= 0.0f) &&
                    (cr * cr <= 3.0f * dt * dt)) {
                    c = 0.0f;
                } else {
                    float cd = (d2 <= 4.0f) ? 0.0f : (fast_sqrt(d2) - 2.0f);
                    float a  = atan2f(fabsf(cr), dt);
                    c = cd + fmaxf(a - YAW_THRESH, 0.0f);
                }
                lmin = fminf(lmin, c);
            }
            lmin = fminf(lmin, __shfl_xor_sync(0xffffffffu, lmin, 16));
            lmin = fminf(lmin, __shfl_xor_sync(0xffffffffu, lmin, 8));
            lmin = fminf(lmin, __shfl_xor_sync(0xffffffffu, lmin, 4));
            lmin = fminf(lmin, __shfl_xor_sync(0xffffffffu, lmin, 2));
            lmin = fminf(lmin, __shfl_xor_sync(0xffffffffu, lmin, 1));
            // nonneg floats: int-bit order == value order -> deterministic
            if (lane == 0) atomicMin(&s_minb[t], __float_as_int(lmin));
        }
        __syncthreads();
    }

    // ---------------- Sum over T (deterministic shfl tree) ----------------
    if (tid < 32) {
        float v = __int_as_float(s_minb[tid]);   // t >= 30 slots hold 0
        v += __shfl_xor_sync(0xffffffffu, v, 16);
        v += __shfl_xor_sync(0xffffffffu, v, 8);
        v += __shfl_xor_sync(0xffffffffu, v, 4);
        v += __shfl_xor_sync(0xffffffffu, v, 2);
        v += __shfl_xor_sync(0xffffffffu, v, 1);
        if (tid == 0) out[bk] = v;
    }
}

extern "C" void kernel_launch(void* const* d_in, const int* in_sizes, int n_in,
                              void* d_out, int out_size) {
    const float* preds = (const float*)d_in[0];
    const float* cn    = (const float*)d_in[1];
    const int*   mask  = (const int*)d_in[2];
    float* out = (float*)d_out;

    consistency_kernel<<<BK, BLOCK>>>(preds, cn, mask, out);
}